// round 12
// baseline (speedup 1.0000x reference)
#include <cuda_runtime.h>
#include <cstdint>

// LIF recurrence: v = alpha*v + beta*c; spike = (v >= 1); v = spike ? 0 : v.
// Sequential over T=2048, parallel over N=32768.
// Output: out[0 : T*N] = spikes, out[T*N : 2*T*N] = voltages (post-reset).
//
// R10 (GRP=16): 133.6us, DRAM 75.2%. R11 (GRP=32, vv[32]) spilled at 255
// regs and regressed. R12: 32-step groups with HALF-flushed voltages
// (vv[16] reused twice -> ~150 regs like R10) + bit-packed spikes flushed
// as one 32-row burst + 32-row cp.async refill bursts. Direction switches:
// 4 per 32 steps (R10: 4 per 16). Outputs use __stcs (write-once).

#define T_STEPS 2048
#define N_NEUR  32768
#define BLOCK   64
#define VEC     4                   // neurons per thread
#define CHUNK   (BLOCK * VEC)       // 256 neurons per CTA (1 KB per stream-row)
#define GRID    (N_NEUR / CHUNK)    // 128 CTAs, 1 per SM
#define STAGES  96                  // smem ring depth (steps) -> 96 KB
#define GRP     32                  // steps per commit group / direction batch
#define HGRP    (GRP / 2)           // voltage half-batch
#define NGRP    (STAGES / GRP)      // 3 groups in flight
#define SMEM_BYTES (STAGES * BLOCK * 16)

__device__ __forceinline__ void cp_async16(unsigned saddr, const float4* gptr)
{
    asm volatile("cp.async.cg.shared.global [%0], [%1], 16;"
                 :: "r"(saddr), "l"(gptr));
}
__device__ __forceinline__ void cp_commit()
{
    asm volatile("cp.async.commit_group;");
}
__device__ __forceinline__ void cp_wait_allow()
{
    asm volatile("cp.async.wait_group %0;" :: "n"(NGRP - 1));
}

__global__ void __launch_bounds__(BLOCK, 1)
lif_kernel(const float* __restrict__ cur,
           const float* __restrict__ v0,
           float* __restrict__ out)
{
    extern __shared__ float4 sbuf[];          // [STAGES * BLOCK]

    const int tid  = threadIdx.x;
    const int base = blockIdx.x * CHUNK + tid * VEC;   // this thread's 4 neurons

    // Reference f32 constants: alpha = f32(exp(-1/20)), beta = f32(1 - alpha)
    const float alpha = (float)0.9512294245007140;
    const float beta  = (float)(1.0 - 0.9512294245007140);

    float4 v = *(const float4*)(v0 + base);

    const float4* cp = (const float4*)(cur + base);        // row stride N_NEUR/4 float4
    float4* sp = (float4*)(out + base);                    // spikes
    float4* vp = (float4*)(out + (size_t)T_STEPS * N_NEUR + base);  // voltages

    const unsigned sbase =
        (unsigned)__cvta_generic_to_shared(sbuf) + (unsigned)tid * 16u;

    // ---- Prime: issue all STAGES stages as NGRP commit groups ----
#pragma unroll
    for (int g = 0; g < NGRP; ++g) {
#pragma unroll
        for (int i = 0; i < GRP; ++i) {
            const int s = g * GRP + i;
            cp_async16(sbase + (unsigned)(s * BLOCK) * 16u,
                       cp + (size_t)s * (N_NEUR / VEC));
        }
        cp_commit();
    }
    cp += (size_t)STAGES * (N_NEUR / VEC);

    // ---- Main loop: one 32-step group per iteration ----
    for (int t = 0; t < T_STEPS; t += GRP) {
        cp_wait_allow();                       // oldest group (steps t..t+31) ready

        const int slot = (t / GRP) % NGRP;
        const int srow0 = slot * GRP;

        uint32_t sbits[GRP / 8] = {0u, 0u, 0u, 0u};
        float4   vv[HGRP];                     // reused for both halves

        // ---- Half 1: steps 0..15 ----
#pragma unroll
        for (int i = 0; i < HGRP; ++i) {
            const float4 c = sbuf[(srow0 + i) * BLOCK + tid];
            // explicitly unfused to match reference rounding
            v.x = __fadd_rn(__fmul_rn(alpha, v.x), __fmul_rn(beta, c.x));
            v.y = __fadd_rn(__fmul_rn(alpha, v.y), __fmul_rn(beta, c.y));
            v.z = __fadd_rn(__fmul_rn(alpha, v.z), __fmul_rn(beta, c.z));
            v.w = __fadd_rn(__fmul_rn(alpha, v.w), __fmul_rn(beta, c.w));
            const bool fx = (v.x >= 1.0f);
            const bool fy = (v.y >= 1.0f);
            const bool fz = (v.z >= 1.0f);
            const bool fw = (v.w >= 1.0f);
            sbits[i >> 3] |= ((fx ? 1u : 0u) | (fy ? 2u : 0u)
                            | (fz ? 4u : 0u) | (fw ? 8u : 0u)) << ((i & 7) * 4);
            v.x = fx ? 0.0f : v.x;
            v.y = fy ? 0.0f : v.y;
            v.z = fz ? 0.0f : v.z;
            v.w = fw ? 0.0f : v.w;
            vv[i] = v;
        }
#pragma unroll
        for (int i = 0; i < HGRP; ++i)
            __stcs(vp + (size_t)i * (N_NEUR / VEC), vv[i]);

        // ---- Half 2: steps 16..31 ----
#pragma unroll
        for (int i = 0; i < HGRP; ++i) {
            const int ii = HGRP + i;
            const float4 c = sbuf[(srow0 + ii) * BLOCK + tid];
            v.x = __fadd_rn(__fmul_rn(alpha, v.x), __fmul_rn(beta, c.x));
            v.y = __fadd_rn(__fmul_rn(alpha, v.y), __fmul_rn(beta, c.y));
            v.z = __fadd_rn(__fmul_rn(alpha, v.z), __fmul_rn(beta, c.z));
            v.w = __fadd_rn(__fmul_rn(alpha, v.w), __fmul_rn(beta, c.w));
            const bool fx = (v.x >= 1.0f);
            const bool fy = (v.y >= 1.0f);
            const bool fz = (v.z >= 1.0f);
            const bool fw = (v.w >= 1.0f);
            sbits[ii >> 3] |= ((fx ? 1u : 0u) | (fy ? 2u : 0u)
                             | (fz ? 4u : 0u) | (fw ? 8u : 0u)) << ((ii & 7) * 4);
            v.x = fx ? 0.0f : v.x;
            v.y = fy ? 0.0f : v.y;
            v.z = fz ? 0.0f : v.z;
            v.w = fw ? 0.0f : v.w;
            vv[i] = v;
        }
#pragma unroll
        for (int i = 0; i < HGRP; ++i)
            __stcs(vp + (size_t)(HGRP + i) * (N_NEUR / VEC), vv[i]);
        vp += (size_t)GRP * (N_NEUR / VEC);

        // ---- Refill this slot for steps t+STAGES..t+STAGES+31 ----
        if (t + STAGES < T_STEPS) {
#pragma unroll
            for (int i = 0; i < GRP; ++i)
                cp_async16(sbase + (unsigned)((srow0 + i) * BLOCK) * 16u,
                           cp + (size_t)i * (N_NEUR / VEC));
            cp += (size_t)GRP * (N_NEUR / VEC);
        }
        cp_commit();                           // empty group near the tail is fine

        // ---- Flush all 32 spike rows as one burst ----
#pragma unroll
        for (int i = 0; i < GRP; ++i) {
            const uint32_t nib = sbits[i >> 3] >> ((i & 7) * 4);
            float4 s4;
            s4.x = (nib & 1u) ? 1.0f : 0.0f;
            s4.y = (nib & 2u) ? 1.0f : 0.0f;
            s4.z = (nib & 4u) ? 1.0f : 0.0f;
            s4.w = (nib & 8u) ? 1.0f : 0.0f;
            __stcs(sp + (size_t)i * (N_NEUR / VEC), s4);
        }
        sp += (size_t)GRP * (N_NEUR / VEC);
    }
}

extern "C" void kernel_launch(void* const* d_in, const int* in_sizes, int n_in,
                              void* d_out, int out_size)
{
    const float* currents = (const float*)d_in[0];   // (T, N) float32
    const float* v0       = (const float*)d_in[1];   // (N,)  float32
    float* out            = (float*)d_out;           // 2*T*N float32

    cudaFuncSetAttribute(lif_kernel,
                         cudaFuncAttributeMaxDynamicSharedMemorySize,
                         SMEM_BYTES);
    lif_kernel<<<GRID, BLOCK, SMEM_BYTES>>>(currents, v0, out);
}

// round 13
// speedup vs baseline: 1.0939x; 1.0939x over previous
#include <cuda_runtime.h>

// LIF recurrence: v = alpha*v + beta*c; spike = (v >= 1); v = spike ? 0 : v.
// Sequential over T=2048, parallel over N=32768.
// Output: out[0 : T*N] = spikes, out[T*N : 2*T*N] = voltages (post-reset).
//
// R10 champion config (133.6us, DRAM 75.2%, regs 148): float4 ops, BLOCK=64,
// GRID=128 (1 CTA/SM on 128 SMs), 64-step cp.async smem ring, 16-step
// direction-batched flushes. R11/R12 (GRP=32 variants) both regressed on
// register pressure -> direction batching is exhausted at GRP=16.
// R13 = R10 + __stcs (evict-first) on the write-once output streams; the
// only remaining unconfounded micro-lever.

#define T_STEPS 2048
#define N_NEUR  32768
#define BLOCK   64
#define VEC     4                   // neurons per thread
#define CHUNK   (BLOCK * VEC)       // 256 neurons per CTA (1 KB per stream-row)
#define GRID    (N_NEUR / CHUNK)    // 128 CTAs, 1 per SM
#define STAGES  64                  // smem ring depth (steps) -> 64 KB
#define GRP     16                  // steps per commit group / direction batch
#define NGRP    (STAGES / GRP)      // 4 groups in flight
#define SMEM_BYTES (STAGES * BLOCK * 16)

__device__ __forceinline__ void cp_async16(unsigned saddr, const float4* gptr)
{
    asm volatile("cp.async.cg.shared.global [%0], [%1], 16;"
                 :: "r"(saddr), "l"(gptr));
}
__device__ __forceinline__ void cp_commit()
{
    asm volatile("cp.async.commit_group;");
}
__device__ __forceinline__ void cp_wait_allow()
{
    asm volatile("cp.async.wait_group %0;" :: "n"(NGRP - 1));
}

__global__ void __launch_bounds__(BLOCK, 1)
lif_kernel(const float* __restrict__ cur,
           const float* __restrict__ v0,
           float* __restrict__ out)
{
    extern __shared__ float4 sbuf[];          // [STAGES * BLOCK]

    const int tid  = threadIdx.x;
    const int base = blockIdx.x * CHUNK + tid * VEC;   // this thread's 4 neurons

    // Reference f32 constants: alpha = f32(exp(-1/20)), beta = f32(1 - alpha)
    const float alpha = (float)0.9512294245007140;
    const float beta  = (float)(1.0 - 0.9512294245007140);

    float4 v = *(const float4*)(v0 + base);

    const float4* cp = (const float4*)(cur + base);        // row stride N_NEUR/4 float4
    float4* sp = (float4*)(out + base);                    // spikes
    float4* vp = (float4*)(out + (size_t)T_STEPS * N_NEUR + base);  // voltages

    const unsigned sbase =
        (unsigned)__cvta_generic_to_shared(sbuf) + (unsigned)tid * 16u;

    // ---- Prime: issue all STAGES stages as NGRP commit groups ----
#pragma unroll
    for (int g = 0; g < NGRP; ++g) {
#pragma unroll
        for (int i = 0; i < GRP; ++i) {
            const int s = g * GRP + i;
            cp_async16(sbase + (unsigned)(s * BLOCK) * 16u,
                       cp + (size_t)s * (N_NEUR / VEC));
        }
        cp_commit();
    }
    cp += (size_t)STAGES * (N_NEUR / VEC);

    // ---- Main loop: one 16-step group per iteration ----
    for (int t = 0; t < T_STEPS; t += GRP) {
        cp_wait_allow();                       // oldest group (steps t..t+15) ready

        const int slot = (t / GRP) & (NGRP - 1);

        // Compute all 16 steps into registers; currents read straight from
        // smem (LDS.128). All reads of this slot complete in program order
        // before the refill cp.async below overwrite it.
        float4 sv[GRP];   // spikes
        float4 vv[GRP];   // post-reset voltages
#pragma unroll
        for (int i = 0; i < GRP; ++i) {
            const float4 c = sbuf[(slot * GRP + i) * BLOCK + tid];
            // explicitly unfused to match reference rounding
            v.x = __fadd_rn(__fmul_rn(alpha, v.x), __fmul_rn(beta, c.x));
            v.y = __fadd_rn(__fmul_rn(alpha, v.y), __fmul_rn(beta, c.y));
            v.z = __fadd_rn(__fmul_rn(alpha, v.z), __fmul_rn(beta, c.z));
            v.w = __fadd_rn(__fmul_rn(alpha, v.w), __fmul_rn(beta, c.w));
            const bool fx = (v.x >= 1.0f);
            const bool fy = (v.y >= 1.0f);
            const bool fz = (v.z >= 1.0f);
            const bool fw = (v.w >= 1.0f);
            sv[i].x = fx ? 1.0f : 0.0f;
            sv[i].y = fy ? 1.0f : 0.0f;
            sv[i].z = fz ? 1.0f : 0.0f;
            sv[i].w = fw ? 1.0f : 0.0f;
            v.x = fx ? 0.0f : v.x;
            v.y = fy ? 0.0f : v.y;
            v.z = fz ? 0.0f : v.z;
            v.w = fw ? 0.0f : v.w;
            vv[i] = v;
        }

        // Refill this slot for steps t+STAGES..t+STAGES+15.
        if (t + STAGES < T_STEPS) {
#pragma unroll
            for (int i = 0; i < GRP; ++i)
                cp_async16(sbase + (unsigned)((slot * GRP + i) * BLOCK) * 16u,
                           cp + (size_t)i * (N_NEUR / VEC));
            cp += (size_t)GRP * (N_NEUR / VEC);
        }
        cp_commit();                           // empty group near the tail is fine

        // Flush stream-by-stream: 16 spike rows, then 16 voltage rows.
        // Evict-first streaming stores: outputs are write-once, never re-read.
#pragma unroll
        for (int i = 0; i < GRP; ++i)
            __stcs(sp + (size_t)i * (N_NEUR / VEC), sv[i]);
        sp += (size_t)GRP * (N_NEUR / VEC);

#pragma unroll
        for (int i = 0; i < GRP; ++i)
            __stcs(vp + (size_t)i * (N_NEUR / VEC), vv[i]);
        vp += (size_t)GRP * (N_NEUR / VEC);
    }
}

extern "C" void kernel_launch(void* const* d_in, const int* in_sizes, int n_in,
                              void* d_out, int out_size)
{
    const float* currents = (const float*)d_in[0];   // (T, N) float32
    const float* v0       = (const float*)d_in[1];   // (N,)  float32
    float* out            = (float*)d_out;           // 2*T*N float32

    cudaFuncSetAttribute(lif_kernel,
                         cudaFuncAttributeMaxDynamicSharedMemorySize,
                         SMEM_BYTES);
    lif_kernel<<<GRID, BLOCK, SMEM_BYTES>>>(currents, v0, out);
}